// round 4
// baseline (speedup 1.0000x reference)
#include <cuda_runtime.h>

// ---------------------------------------------------------------------------
// ResonantComplexProjection
//   theta[b,n,i] = x[b,i] / (1+|W[n,i]|) + B[n,i]
//   idx = floor(theta * 4096/2pi) mod 4096   (LUT sin/cos, 4096 entries)
//   cos_sum[b,n] = sum_i cos_lut[idx];  sin_sum likewise
//   real = cos_sum @ Wr^T ; imag = sin_sum @ Wi^T
// Shapes: batch=256, in_f=512, n_neur=1024, out_f=512
// Inputs (metadata order): x, W, B, Wr, Wi. Output: [real(256x512), imag(256x512)]
// ---------------------------------------------------------------------------

#define LUT_HALF 4608                 // table covers k in [-4608, 4608)
#define LUT_N    (2 * LUT_HALF)       // 9216 entries (float2: sin, cos)
#define SMEM_MAIN (LUT_N * 8 + 8192)  // 72KB LUT + 8KB x tile = 81920 B

static __device__ float4 g_lut4[LUT_N / 2];       // 2 (sin,cos) entries per float4
static __device__ float2 g_rs[256 * 1024];        // [ipair][n] -> {S/(1+|W|) at i=2ip, 2ip+1}
static __device__ float2 g_bs[256 * 1024];        // [ipair][n] -> {S*B - 0.5 at i=2ip, 2ip+1}
static __device__ float2 g_sums[2 * 256 * 1024];  // [half][b][n] -> (sin_sum, cos_sum) partials

// ---------------------------------------------------------------------------
// Init kernels (run every launch; ~10us total)
// ---------------------------------------------------------------------------

__global__ void k_init_lut() {
    int t = blockIdx.x * 256 + threadIdx.x;       // < 4608
    const float step = (float)(6.283185307179586476925287 / 4096.0);
    int k0 = 2 * t - LUT_HALF;
    int j0 = k0 & 4095;                            // floor-mod 4096 (matches Python %)
    int j1 = (k0 + 1) & 4095;
    float a0 = (float)j0 * step;
    float a1 = (float)j1 * step;
    float4 e;
    e.x = sinf(a0); e.y = cosf(a0);
    e.z = sinf(a1); e.w = cosf(a1);
    g_lut4[t] = e;
}

__global__ void k_init_rb(const float* __restrict__ W, const float* __restrict__ B) {
    int e = blockIdx.x * 256 + threadIdx.x;       // < 262144 = 256 ipairs * 1024 n
    int n  = e & 1023;
    int ip = e >> 10;
    const float S = (float)(4096.0 / 6.283185307179586476925287);
    float2 w = ((const float2*)(W + n * 512))[ip];
    float2 b = ((const float2*)(B + n * 512))[ip];
    float2 rs, bs;
    rs.x = S / (1.0f + fabsf(w.x));
    rs.y = S / (1.0f + fabsf(w.y));
    bs.x = S * b.x - 0.5f;                        // fold floor(v)=round(v-0.5) shift in
    bs.y = S * b.y - 0.5f;
    g_rs[e] = rs;
    g_bs[e] = bs;
}

// ---------------------------------------------------------------------------
// Packed f32x2 helpers
// ---------------------------------------------------------------------------

__device__ __forceinline__ unsigned long long fma2_(unsigned long long a,
                                                    unsigned long long b,
                                                    unsigned long long c) {
    unsigned long long d;
    asm("fma.rn.f32x2 %0, %1, %2, %3;" : "=l"(d) : "l"(a), "l"(b), "l"(c));
    return d;
}
__device__ __forceinline__ unsigned long long add2_(unsigned long long a,
                                                    unsigned long long b) {
    unsigned long long d;
    asm("add.rn.f32x2 %0, %1, %2;" : "=l"(d) : "l"(a), "l"(b));
    return d;
}
__device__ __forceinline__ unsigned long long lds64_(unsigned a) {
    unsigned long long v;
    asm("ld.shared.b64 %0, [%1];" : "=l"(v) : "r"(a));
    return v;
}

// ---------------------------------------------------------------------------
// Main kernel: grid (4 n-tiles, 32 batch-groups, 2 i-halves), 256 threads.
// Thread = 1 neuron x 8 batches x 256 i (as 128 i-pairs).
// Magic-number floor: v + 1.5*2^23 (RN) puts round(v) in low mantissa bits;
// bits*8 + cbase lands directly on the extended shared LUT entry:
//   addr = (0x4B400000 + m)*8 + (smem + 4608*8 - 0x5A000000) = smem + (m+4608)*8
// ---------------------------------------------------------------------------

__global__ __launch_bounds__(256, 2) void k_main(const float* __restrict__ x) {
    extern __shared__ unsigned char smem[];
    float4* lut4 = (float4*)smem;
    unsigned long long* xs2 = (unsigned long long*)(smem + LUT_N * 8);  // [8 b][128 ipair]

    const int tid = threadIdx.x;
    const int nt = blockIdx.x, bg = blockIdx.y, h = blockIdx.z;

    // Stage LUT (72KB) into shared
#pragma unroll
    for (int t = 0; t < (LUT_N / 2) / 256; t++)        // 18 iters
        lut4[tid + t * 256] = g_lut4[tid + t * 256];

    // Stage this block's x slice: 8 batches x 128 i-pairs
    const unsigned long long* xg = (const unsigned long long*)x;
#pragma unroll
    for (int t = 0; t < 4; t++) {
        int e = tid + t * 256;                          // < 1024
        int lb = e >> 7, ipl = e & 127;
        xs2[e] = xg[(bg * 8 + lb) * 256 + h * 128 + ipl];
    }
    __syncthreads();

    const int n = (nt << 8) + tid;
    const unsigned long long* rsp =
        ((const unsigned long long*)g_rs) + (size_t)(h * 128) * 1024 + n;
    const unsigned long long* bsp =
        ((const unsigned long long*)g_bs) + (size_t)(h * 128) * 1024 + n;

    const unsigned cbase =
        (unsigned)__cvta_generic_to_shared(smem) + (unsigned)(LUT_HALF * 8) - 0x5A000000u;
    const unsigned long long MAGIC2 = 0x4B4000004B400000ULL;   // {1.5*2^23, 1.5*2^23}

    unsigned long long acc[8];
#pragma unroll
    for (int b = 0; b < 8; b++) acc[b] = 0ULL;

#pragma unroll 2
    for (int ip = 0; ip < 128; ip++) {
        unsigned long long rs2 = __ldg(rsp + ip * 1024);   // packed {rs(2i), rs(2i+1)}
        unsigned long long bs2 = __ldg(bsp + ip * 1024);
#pragma unroll
        for (int b = 0; b < 8; b++) {
            unsigned long long xp = xs2[b * 128 + ip];      // broadcast LDS.64
            unsigned long long w  = add2_(fma2_(xp, rs2, bs2), MAGIC2);
            unsigned lo, hi;
            asm("mov.b64 {%0, %1}, %2;" : "=r"(lo), "=r"(hi) : "l"(w));  // free reg split
            unsigned long long e0 = lds64_(lo * 8u + cbase);
            unsigned long long e1 = lds64_(hi * 8u + cbase);
            acc[b] = add2_(acc[b], e0);
            acc[b] = add2_(acc[b], e1);
        }
    }

    unsigned long long* sp =
        ((unsigned long long*)g_sums) + (size_t)h * 262144 + (size_t)(bg * 8) * 1024 + n;
#pragma unroll
    for (int b = 0; b < 8; b++) sp[b * 1024] = acc[b];
}

// ---------------------------------------------------------------------------
// Epilogue GEMMs: real = cos_sum @ Wr^T, imag = sin_sum @ Wi^T
// 32x32 output tile per block, K=1024 (sums the two i-half partials on load).
// ---------------------------------------------------------------------------

__global__ __launch_bounds__(256) void k_gemm(const float* __restrict__ Wr,
                                              const float* __restrict__ Wi,
                                              float* __restrict__ out) {
    __shared__ float sC[32][33];
    __shared__ float sS[32][33];
    __shared__ float sR[32][33];
    __shared__ float sI[32][33];

    const int b0 = blockIdx.x << 5;
    const int o0 = blockIdx.y << 5;
    const int tid = threadIdx.x;
    const int tx = tid & 15, ty = tid >> 4;

    float aR[2][2] = {{0.f, 0.f}, {0.f, 0.f}};
    float aI[2][2] = {{0.f, 0.f}, {0.f, 0.f}};

    const float2* s0p = g_sums;
    const float2* s1p = g_sums + 262144;

    for (int k0 = 0; k0 < 1024; k0 += 32) {
#pragma unroll
        for (int j = 0; j < 4; j++) {
            int e = tid + (j << 8);
            int nl = e & 31, rl = e >> 5;
            float2 p0 = s0p[(size_t)(b0 + rl) * 1024 + k0 + nl];
            float2 p1 = s1p[(size_t)(b0 + rl) * 1024 + k0 + nl];
            sC[nl][rl] = p0.y + p1.y;     // cos
            sS[nl][rl] = p0.x + p1.x;     // sin
            sR[nl][rl] = Wr[(size_t)(o0 + rl) * 1024 + k0 + nl];
            sI[nl][rl] = Wi[(size_t)(o0 + rl) * 1024 + k0 + nl];
        }
        __syncthreads();
#pragma unroll
        for (int k = 0; k < 32; k++) {
            float c0 = sC[k][ty * 2], c1 = sC[k][ty * 2 + 1];
            float s0 = sS[k][ty * 2], s1 = sS[k][ty * 2 + 1];
            float r0 = sR[k][tx * 2], r1 = sR[k][tx * 2 + 1];
            float i0 = sI[k][tx * 2], i1 = sI[k][tx * 2 + 1];
            aR[0][0] = fmaf(c0, r0, aR[0][0]);
            aR[0][1] = fmaf(c0, r1, aR[0][1]);
            aR[1][0] = fmaf(c1, r0, aR[1][0]);
            aR[1][1] = fmaf(c1, r1, aR[1][1]);
            aI[0][0] = fmaf(s0, i0, aI[0][0]);
            aI[0][1] = fmaf(s0, i1, aI[0][1]);
            aI[1][0] = fmaf(s1, i0, aI[1][0]);
            aI[1][1] = fmaf(s1, i1, aI[1][1]);
        }
        __syncthreads();
    }

    const int b = b0 + ty * 2, o = o0 + tx * 2;
    float* ore = out;
    float* oim = out + 131072;  // 256*512
#pragma unroll
    for (int i = 0; i < 2; i++)
#pragma unroll
        for (int j = 0; j < 2; j++) {
            ore[(size_t)(b + i) * 512 + o + j] = aR[i][j];
            oim[(size_t)(b + i) * 512 + o + j] = aI[i][j];
        }
}

// ---------------------------------------------------------------------------

extern "C" void kernel_launch(void* const* d_in, const int* in_sizes, int n_in,
                              void* d_out, int out_size) {
    const float* x  = (const float*)d_in[0];
    const float* W  = (const float*)d_in[1];
    const float* B  = (const float*)d_in[2];
    const float* Wr = (const float*)d_in[3];
    const float* Wi = (const float*)d_in[4];
    float* out = (float*)d_out;

    cudaFuncSetAttribute(k_main, cudaFuncAttributeMaxDynamicSharedMemorySize, SMEM_MAIN);

    k_init_lut<<<18, 256>>>();
    k_init_rb<<<1024, 256>>>(W, B);
    k_main<<<dim3(4, 32, 2), 256, SMEM_MAIN>>>(x);
    k_gemm<<<dim3(8, 16), 256>>>(Wr, Wi, out);
}

// round 5
// speedup vs baseline: 1.6037x; 1.6037x over previous
#include <cuda_runtime.h>

// ---------------------------------------------------------------------------
// ResonantComplexProjection
//   theta[b,n,i] = x[b,i] / (1+|W[n,i]|) + B[n,i]
//   idx = floor(theta * 4096/2pi) mod 4096   (LUT sin/cos, 4096 entries)
//   cos_sum[b,n] = sum_i cos_lut[idx];  sin_sum likewise
//   real = cos_sum @ Wr^T ; imag = sin_sum @ Wi^T
// Shapes: batch=256, in_f=512, n_neur=1024, out_f=512
// Inputs (metadata order): x, W, B, Wr, Wi. Output: [real(256x512), imag(256x512)]
// ---------------------------------------------------------------------------

#define LUT_HALF 4608                 // table covers k in [-4608, 4608)
#define LUT_N    (2 * LUT_HALF)       // 9216 entries (float2: sin, cos)
#define SMEM_MAIN (LUT_N * 8 + 8192)  // 72KB LUT + 8KB x tile = 81920 B

static __device__ float4 g_lut4[LUT_N / 2];       // 2 (sin,cos) entries per float4
static __device__ float2 g_rs[256 * 1024];        // [ipair][n] -> {S/(1+|W|) at i=2ip, 2ip+1}
static __device__ float2 g_bs[256 * 1024];        // [ipair][n] -> {S*B - 0.5 at i=2ip, 2ip+1}
static __device__ float2 g_sums[2 * 256 * 1024];  // [half][b][n] -> (sin_sum, cos_sum) partials
static __device__ float  g_part[4][262144];       // [ksplit][p*131072 + b*512 + o]

// ---------------------------------------------------------------------------
// Init kernels (run every launch; ~10us total)
// ---------------------------------------------------------------------------

__global__ void k_init_lut() {
    int t = blockIdx.x * 256 + threadIdx.x;       // < 4608
    const float step = (float)(6.283185307179586476925287 / 4096.0);
    int k0 = 2 * t - LUT_HALF;
    int j0 = k0 & 4095;                            // floor-mod 4096 (matches Python %)
    int j1 = (k0 + 1) & 4095;
    float a0 = (float)j0 * step;
    float a1 = (float)j1 * step;
    float4 e;
    e.x = sinf(a0); e.y = cosf(a0);
    e.z = sinf(a1); e.w = cosf(a1);
    g_lut4[t] = e;
}

__global__ void k_init_rb(const float* __restrict__ W, const float* __restrict__ B) {
    int e = blockIdx.x * 256 + threadIdx.x;       // < 262144 = 256 ipairs * 1024 n
    int n  = e & 1023;
    int ip = e >> 10;
    const float S = (float)(4096.0 / 6.283185307179586476925287);
    float2 w = ((const float2*)(W + n * 512))[ip];
    float2 b = ((const float2*)(B + n * 512))[ip];
    float2 rs, bs;
    rs.x = S / (1.0f + fabsf(w.x));
    rs.y = S / (1.0f + fabsf(w.y));
    bs.x = S * b.x - 0.5f;                        // fold floor(v)=round(v-0.5) shift in
    bs.y = S * b.y - 0.5f;
    g_rs[e] = rs;
    g_bs[e] = bs;
}

// ---------------------------------------------------------------------------
// Packed f32x2 helpers
// ---------------------------------------------------------------------------

__device__ __forceinline__ unsigned long long fma2_(unsigned long long a,
                                                    unsigned long long b,
                                                    unsigned long long c) {
    unsigned long long d;
    asm("fma.rn.f32x2 %0, %1, %2, %3;" : "=l"(d) : "l"(a), "l"(b), "l"(c));
    return d;
}
__device__ __forceinline__ unsigned long long add2_(unsigned long long a,
                                                    unsigned long long b) {
    unsigned long long d;
    asm("add.rn.f32x2 %0, %1, %2;" : "=l"(d) : "l"(a), "l"(b));
    return d;
}
__device__ __forceinline__ unsigned long long lds64_(unsigned a) {
    unsigned long long v;
    asm("ld.shared.b64 %0, [%1];" : "=l"(v) : "r"(a));
    return v;
}

// ---------------------------------------------------------------------------
// Main kernel (UNCHANGED from passing R3 version):
// grid (4 n-tiles, 32 batch-groups, 2 i-halves), 256 threads.
// Thread = 1 neuron x 8 batches x 256 i (as 128 i-pairs).
// Magic-number floor: v + 1.5*2^23 (RN) puts round(v) in low mantissa bits;
// bits*8 + cbase lands directly on the extended shared LUT entry.
// ---------------------------------------------------------------------------

__global__ __launch_bounds__(256, 2) void k_main(const float* __restrict__ x) {
    extern __shared__ unsigned char smem[];
    float4* lut4 = (float4*)smem;
    unsigned long long* xs2 = (unsigned long long*)(smem + LUT_N * 8);  // [8 b][128 ipair]

    const int tid = threadIdx.x;
    const int nt = blockIdx.x, bg = blockIdx.y, h = blockIdx.z;

    // Stage LUT (72KB) into shared
#pragma unroll
    for (int t = 0; t < (LUT_N / 2) / 256; t++)        // 18 iters
        lut4[tid + t * 256] = g_lut4[tid + t * 256];

    // Stage this block's x slice: 8 batches x 128 i-pairs
    const unsigned long long* xg = (const unsigned long long*)x;
#pragma unroll
    for (int t = 0; t < 4; t++) {
        int e = tid + t * 256;                          // < 1024
        int lb = e >> 7, ipl = e & 127;
        xs2[e] = xg[(bg * 8 + lb) * 256 + h * 128 + ipl];
    }
    __syncthreads();

    const int n = (nt << 8) + tid;
    const unsigned long long* rsp =
        ((const unsigned long long*)g_rs) + (size_t)(h * 128) * 1024 + n;
    const unsigned long long* bsp =
        ((const unsigned long long*)g_bs) + (size_t)(h * 128) * 1024 + n;

    const unsigned cbase =
        (unsigned)__cvta_generic_to_shared(smem) + (unsigned)(LUT_HALF * 8) - 0x5A000000u;
    const unsigned long long MAGIC2 = 0x4B4000004B400000ULL;   // {1.5*2^23, 1.5*2^23}

    unsigned long long acc[8];
#pragma unroll
    for (int b = 0; b < 8; b++) acc[b] = 0ULL;

#pragma unroll 2
    for (int ip = 0; ip < 128; ip++) {
        unsigned long long rs2 = __ldg(rsp + ip * 1024);   // packed {rs(2i), rs(2i+1)}
        unsigned long long bs2 = __ldg(bsp + ip * 1024);
#pragma unroll
        for (int b = 0; b < 8; b++) {
            unsigned long long xp = xs2[b * 128 + ip];      // uniform-addr broadcast LDS.64
            unsigned long long w  = add2_(fma2_(xp, rs2, bs2), MAGIC2);
            unsigned lo, hi;
            asm("mov.b64 {%0, %1}, %2;" : "=r"(lo), "=r"(hi) : "l"(w));
            unsigned long long e0 = lds64_(lo * 8u + cbase);
            unsigned long long e1 = lds64_(hi * 8u + cbase);
            acc[b] = add2_(acc[b], e0);
            acc[b] = add2_(acc[b], e1);
        }
    }

    unsigned long long* sp =
        ((unsigned long long*)g_sums) + (size_t)h * 262144 + (size_t)(bg * 8) * 1024 + n;
#pragma unroll
    for (int b = 0; b < 8; b++) sp[b * 1024] = acc[b];
}

// ---------------------------------------------------------------------------
// Epilogue GEMM v2: split-K fp32 GEMM.
//   real = cos_sum @ Wr^T, imag = sin_sum @ Wi^T  (K = n_neur = 1024)
// Block: 64x64 output tile, one of {real,imag} (p), one K-split of 256 (s).
// grid (4 b-tiles, 8 o-tiles, 8 = p*4+s) = 256 blocks, 256 threads.
// Thread: 4x4 microtile -> inner loop is 2 LDS.128 per 16 FMA.
// Partials to g_part; fixed-order reduce for determinism.
// ---------------------------------------------------------------------------

__global__ __launch_bounds__(256, 2) void k_gemm2(const float* __restrict__ Wr,
                                                  const float* __restrict__ Wi) {
    __shared__ float As[16][68];   // [kk][b]  pad 68: aligned float4 rows, mild conflicts
    __shared__ float Bs[16][68];   // [kk][o]

    const int tid = threadIdx.x;
    const int b0 = blockIdx.x << 6;
    const int o0 = blockIdx.y << 6;
    const int z  = blockIdx.z;
    const int pp = z >> 2;               // 0 = real(cos), 1 = imag(sin)
    const int s  = z & 3;                // K-split

    const float* Wp = pp ? Wi : Wr;
    const float2* s0p = g_sums;          // i-half 0 partials
    const float2* s1p = g_sums + 262144; // i-half 1 partials

    const int tx = tid & 15, ty = tid >> 4;

    float acc[4][4] = {};

    const int kbase = s << 8;            // 256 K per split
    for (int kc = 0; kc < 16; kc++) {
        const int k0 = kbase + (kc << 4);
#pragma unroll
        for (int t = 0; t < 4; t++) {
            int e = tid + (t << 8);
            int kk = e & 15, m = e >> 4;            // 16 consecutive k per 16 threads
            float2 p0 = s0p[(size_t)(b0 + m) * 1024 + k0 + kk];
            float2 p1 = s1p[(size_t)(b0 + m) * 1024 + k0 + kk];
            As[kk][m] = pp ? (p0.x + p1.x) : (p0.y + p1.y);
            Bs[kk][m] = Wp[(size_t)(o0 + m) * 1024 + k0 + kk];
        }
        __syncthreads();
#pragma unroll
        for (int kk = 0; kk < 16; kk++) {
            float4 a4 = *(const float4*)&As[kk][ty << 2];   // broadcast within warp
            float4 b4 = *(const float4*)&Bs[kk][tx << 2];
            float av[4] = {a4.x, a4.y, a4.z, a4.w};
            float bv[4] = {b4.x, b4.y, b4.z, b4.w};
#pragma unroll
            for (int i = 0; i < 4; i++)
#pragma unroll
                for (int j = 0; j < 4; j++)
                    acc[i][j] = fmaf(av[i], bv[j], acc[i][j]);
        }
        __syncthreads();
    }

    float* dst = &g_part[s][pp * 131072 + (size_t)(b0 + (ty << 2)) * 512 + o0 + (tx << 2)];
#pragma unroll
    for (int i = 0; i < 4; i++)
        *(float4*)(dst + i * 512) =
            make_float4(acc[i][0], acc[i][1], acc[i][2], acc[i][3]);
}

__global__ void k_reduce(float* __restrict__ out) {
    int idx = blockIdx.x * 256 + threadIdx.x;   // < 262144
    // Fixed summation order -> bitwise deterministic
    out[idx] = (g_part[0][idx] + g_part[1][idx]) + (g_part[2][idx] + g_part[3][idx]);
}

// ---------------------------------------------------------------------------

extern "C" void kernel_launch(void* const* d_in, const int* in_sizes, int n_in,
                              void* d_out, int out_size) {
    const float* x  = (const float*)d_in[0];
    const float* W  = (const float*)d_in[1];
    const float* B  = (const float*)d_in[2];
    const float* Wr = (const float*)d_in[3];
    const float* Wi = (const float*)d_in[4];
    float* out = (float*)d_out;

    cudaFuncSetAttribute(k_main, cudaFuncAttributeMaxDynamicSharedMemorySize, SMEM_MAIN);

    k_init_lut<<<18, 256>>>();
    k_init_rb<<<1024, 256>>>(W, B);
    k_main<<<dim3(4, 32, 2), 256, SMEM_MAIN>>>(x);
    k_gemm2<<<dim3(4, 8, 8), 256>>>(Wr, Wi);
    k_reduce<<<1024, 256>>>(out);
}